// round 1
// baseline (speedup 1.0000x reference)
#include <cuda_runtime.h>

typedef unsigned long long ull;

#define HH 512
#define WW 1024
#define NPX (HH * WW)        // 524288 HR pixels
#define LRN (256 * 512)      // LR plane size

// ---------------- transposed weight staging (global scratch) ----------------
__device__ __align__(16) float g_w0t[128 * 128];  // [k=128][j=128]
__device__ __align__(16) float g_w1t[128 * 64];   // [k=128][j=64]
__device__ __align__(16) float g_w2t[64 * 32];    // [k=64][j=32]
__device__ __align__(16) float g_w3t[32 * 16];    // [k=32][j=16]
__device__ __align__(16) float g_w4t[16 * 8];     // [k=16][j=8]

// ---------------- packed f32x2 helpers (sm_100+ PTX) ----------------
__device__ __forceinline__ ull pk2(float lo, float hi) {
    ull r; asm("mov.b64 %0, {%1, %2};" : "=l"(r) : "f"(lo), "f"(hi)); return r;
}
__device__ __forceinline__ void upk(ull v, float& lo, float& hi) {
    asm("mov.b64 {%0, %1}, %2;" : "=f"(lo), "=f"(hi) : "l"(v));
}
__device__ __forceinline__ void fma2(ull& d, ull a, ull b) {
    asm("fma.rn.f32x2 %0, %1, %2, %0;" : "+l"(d) : "l"(a), "l"(b));
}
__device__ __forceinline__ float lrelu(float x) { return fmaxf(x, 0.01f * x); }

// ---------------- prep: transpose all MLP weights once per launch ----------------
__global__ void cmfsm_prep(const float* __restrict__ w0, const float* __restrict__ w1,
                           const float* __restrict__ w2, const float* __restrict__ w3,
                           const float* __restrict__ w4) {
    int t = blockIdx.x * blockDim.x + threadIdx.x;
    int n = gridDim.x * blockDim.x;
    for (int i = t; i < 128 * 128; i += n) { int j = i >> 7, k = i & 127; g_w0t[k * 128 + j] = w0[i]; }
    for (int i = t; i < 64 * 128;  i += n) { int j = i >> 7, k = i & 127; g_w1t[k * 64  + j] = w1[i]; }
    for (int i = t; i < 32 * 64;   i += n) { int j = i >> 6, k = i & 63;  g_w2t[k * 32  + j] = w2[i]; }
    for (int i = t; i < 16 * 32;   i += n) { int j = i >> 5, k = i & 31;  g_w3t[k * 16  + j] = w3[i]; }
    for (int i = t; i < 8 * 16;    i += n) { int j = i >> 4, k = i & 15;  g_w4t[k * 8   + j] = w4[i]; }
}

// ---------------- shared memory layout (floats) ----------------
// X: 64-deep activation buffer, one private column per thread (conflict-free)
#define SM_X   0
#define SM_W0  (SM_X  + 64 * 256)       // 16384
#define SM_W1  (SM_W0 + 128 * 128)      // +16384
#define SM_W2  (SM_W1 + 128 * 64)       // +8192
#define SM_W3  (SM_W2 + 64 * 32)        // +2048
#define SM_W4  (SM_W3 + 32 * 16)        // +512
#define SM_TOT (SM_W4 + 16 * 8)         // +128 -> 43648 floats = 174592 B

__global__ void __launch_bounds__(256, 1)
cmfsm_main(const float* __restrict__ lr, const float* __restrict__ hr,
           const float* __restrict__ w5, const float* __restrict__ s2w0,
           const float* __restrict__ s2w1, const float* __restrict__ s2w2,
           const float* __restrict__ fw, float* __restrict__ out) {
    extern __shared__ __align__(16) float smem[];
    float* X    = smem + SM_X;
    float* sw0t = smem + SM_W0;
    float* sw1t = smem + SM_W1;
    float* sw2t = smem + SM_W2;
    float* sw3t = smem + SM_W3;
    float* sw4t = smem + SM_W4;

    const int tid = threadIdx.x;

    // coalesced, conflict-free weight copy into smem (float4)
    {
        const float4* s0 = (const float4*)g_w0t; float4* d0 = (float4*)sw0t;
        for (int i = tid; i < (128 * 128) / 4; i += 256) d0[i] = s0[i];
        const float4* s1 = (const float4*)g_w1t; float4* d1 = (float4*)sw1t;
        for (int i = tid; i < (128 * 64) / 4; i += 256) d1[i] = s1[i];
        const float4* s2 = (const float4*)g_w2t; float4* d2 = (float4*)sw2t;
        for (int i = tid; i < (64 * 32) / 4; i += 256) d2[i] = s2[i];
        const float4* s3 = (const float4*)g_w3t; float4* d3 = (float4*)sw3t;
        for (int i = tid; i < (32 * 16) / 4; i += 256) d3[i] = s3[i];
        const float4* s4 = (const float4*)g_w4t; float4* d4 = (float4*)sw4t;
        for (int i = tid; i < (16 * 8) / 4; i += 256) d4[i] = s4[i];
    }
    __syncthreads();

    const int px = blockIdx.x * 256 + tid;
    const int h = px >> 10;
    const int w = px & 1023;
    const int lidx = ((h >> 1) << 9) + (w >> 1);

    // stage lr (rows 0..31) and hr (rows 32..63) into private X columns
#pragma unroll
    for (int c = 0; c < 32; c++) X[c * 256 + tid] = lr[c * LRN + lidx];
#pragma unroll
    for (int c = 0; c < 32; c++) X[(32 + c) * 256 + tid] = hr[c * NPX + px];

    // ---------------- layer 1: 128 <- rep(128) ----------------
    ull A1[64];
#pragma unroll
    for (int i = 0; i < 64; i++) A1[i] = 0ull;
#pragma unroll 1
    for (int k = 0; k < 32; k++) {
        float av = X[k * 256 + tid];
        float bv = X[(32 + k) * 256 + tid];
        float dv = av - bv;
        ull ad = pk2(av, av), bd = pk2(bv, bv);
        ull pd = pk2(av * bv, av * bv), qd = pk2(dv * dv, dv * dv);
        const ulonglong2* wa = (const ulonglong2*)(sw0t + k * 128);
        const ulonglong2* wb = (const ulonglong2*)(sw0t + (32 + k) * 128);
        const ulonglong2* wp = (const ulonglong2*)(sw0t + (64 + k) * 128);
        const ulonglong2* wq = (const ulonglong2*)(sw0t + (96 + k) * 128);
#pragma unroll
        for (int p = 0; p < 32; p++) {
            ulonglong2 va = wa[p], vb = wb[p], vp = wp[p], vq = wq[p];
            fma2(A1[2 * p], va.x, ad); fma2(A1[2 * p + 1], va.y, ad);
            fma2(A1[2 * p], vb.x, bd); fma2(A1[2 * p + 1], vb.y, bd);
            fma2(A1[2 * p], vp.x, pd); fma2(A1[2 * p + 1], vp.y, pd);
            fma2(A1[2 * p], vq.x, qd); fma2(A1[2 * p + 1], vq.y, qd);
        }
    }

    // ---------------- layer 2: 64 <- leaky(o1)(128), two 64-deep passes ----------------
    ull A2[32];
#pragma unroll
    for (int i = 0; i < 32; i++) A2[i] = 0ull;
#pragma unroll
    for (int half = 0; half < 2; half++) {
#pragma unroll
        for (int i = 0; i < 32; i++) {
            float lo, hi; upk(A1[half * 32 + i], lo, hi);
            X[(2 * i) * 256 + tid]     = lrelu(lo);
            X[(2 * i + 1) * 256 + tid] = lrelu(hi);
        }
#pragma unroll 1
        for (int k = 0; k < 64; k++) {
            float x = X[k * 256 + tid];
            ull xd = pk2(x, x);
            const ulonglong2* wr = (const ulonglong2*)(sw1t + (half * 64 + k) * 64);
#pragma unroll
            for (int p = 0; p < 16; p++) {
                ulonglong2 v = wr[p];
                fma2(A2[2 * p], v.x, xd); fma2(A2[2 * p + 1], v.y, xd);
            }
        }
    }

    // ---------------- layer 3: 32 <- leaky(o2)(64) ----------------
    ull A3[16];
#pragma unroll
    for (int i = 0; i < 16; i++) A3[i] = 0ull;
#pragma unroll
    for (int i = 0; i < 32; i++) {
        float lo, hi; upk(A2[i], lo, hi);
        X[(2 * i) * 256 + tid]     = lrelu(lo);
        X[(2 * i + 1) * 256 + tid] = lrelu(hi);
    }
#pragma unroll 1
    for (int k = 0; k < 64; k++) {
        float x = X[k * 256 + tid];
        ull xd = pk2(x, x);
        const ulonglong2* wr = (const ulonglong2*)(sw2t + k * 32);
#pragma unroll
        for (int p = 0; p < 8; p++) {
            ulonglong2 v = wr[p];
            fma2(A3[2 * p], v.x, xd); fma2(A3[2 * p + 1], v.y, xd);
        }
    }

    // ---------------- layer 4: 16 <- leaky(o3)(32) ----------------
    ull A4[8];
#pragma unroll
    for (int i = 0; i < 8; i++) A4[i] = 0ull;
#pragma unroll
    for (int i = 0; i < 16; i++) {
        float lo, hi; upk(A3[i], lo, hi);
        X[(2 * i) * 256 + tid]     = lrelu(lo);
        X[(2 * i + 1) * 256 + tid] = lrelu(hi);
    }
#pragma unroll 1
    for (int k = 0; k < 32; k++) {
        float x = X[k * 256 + tid];
        ull xd = pk2(x, x);
        const ulonglong2* wr = (const ulonglong2*)(sw3t + k * 16);
#pragma unroll
        for (int p = 0; p < 4; p++) {
            ulonglong2 v = wr[p];
            fma2(A4[2 * p], v.x, xd); fma2(A4[2 * p + 1], v.y, xd);
        }
    }

    // ---------------- layer 5: 8 <- leaky(o4)(16), NO activation on output ----------------
    ull A5[4];
#pragma unroll
    for (int i = 0; i < 4; i++) A5[i] = 0ull;
#pragma unroll
    for (int i = 0; i < 8; i++) {
        float lo, hi; upk(A4[i], lo, hi);
        X[(2 * i) * 256 + tid]     = lrelu(lo);
        X[(2 * i + 1) * 256 + tid] = lrelu(hi);
    }
#pragma unroll 1
    for (int k = 0; k < 16; k++) {
        float x = X[k * 256 + tid];
        ull xd = pk2(x, x);
        const ulonglong2* wr = (const ulonglong2*)(sw4t + k * 8);
#pragma unroll
        for (int p = 0; p < 2; p++) {
            ulonglong2 v = wr[p];
            fma2(A5[2 * p], v.x, xd); fma2(A5[2 * p + 1], v.y, xd);
        }
    }

    // ---------------- layer 6: weights1 = w5 . o5 ----------------
    float o5[8];
#pragma unroll
    for (int i = 0; i < 4; i++) upk(A5[i], o5[2 * i], o5[2 * i + 1]);
    float w1v = 0.f;
#pragma unroll
    for (int m = 0; m < 8; m++) w1v += w5[m] * o5[m];

    // ---------------- weights2: tiny MLP on (dx, dy, sqrt(2)) parity pattern ----------------
    float dx = (w & 1) ? 1.0f : -1.0f;
    float dy = (h & 1) ? 1.0f : -1.0f;
    const float nm = 1.41421356237309515f;
    float t0 = lrelu(s2w0[0] * dx + s2w0[1] * dy + s2w0[2] * nm);
    float t1 = lrelu(s2w0[3] * dx + s2w0[4] * dy + s2w0[5] * nm);
    float t2 = lrelu(s2w0[6] * dx + s2w0[7] * dy + s2w0[8] * nm);
    float u0 = lrelu(s2w1[0] * t0 + s2w1[1] * t1 + s2w1[2] * t2);
    float u1 = lrelu(s2w1[3] * t0 + s2w1[4] * t1 + s2w1[5] * t2);
    float w2v = s2w2[0] * u0 + s2w2[1] * u1;

    out[px] = fabsf(fw[0]) * w1v + fabsf(fw[1]) * w2v;
}

extern "C" void kernel_launch(void* const* d_in, const int* in_sizes, int n_in,
                              void* d_out, int out_size) {
    const float* lr   = (const float*)d_in[0];
    const float* hr   = (const float*)d_in[1];
    const float* w0   = (const float*)d_in[2];
    const float* w1   = (const float*)d_in[3];
    const float* w2   = (const float*)d_in[4];
    const float* w3   = (const float*)d_in[5];
    const float* w4   = (const float*)d_in[6];
    const float* w5   = (const float*)d_in[7];
    const float* s2w0 = (const float*)d_in[8];
    const float* s2w1 = (const float*)d_in[9];
    const float* s2w2 = (const float*)d_in[10];
    const float* fw   = (const float*)d_in[11];

    cmfsm_prep<<<64, 256>>>(w0, w1, w2, w3, w4);

    size_t smem_bytes = (size_t)SM_TOT * sizeof(float);
    cudaFuncSetAttribute(cmfsm_main, cudaFuncAttributeMaxDynamicSharedMemorySize,
                         (int)smem_bytes);
    cmfsm_main<<<NPX / 256, 256, smem_bytes>>>(lr, hr, w5, s2w0, s2w1, s2w2, fw,
                                               (float*)d_out);
}

// round 2
// speedup vs baseline: 1.2216x; 1.2216x over previous
#include <cuda_runtime.h>

typedef unsigned long long ull;

#define NPX (512 * 1024)
#define LRN (256 * 512)
#define SX  260               // X row stride in floats (1040B, 16B aligned)

// ---------------- swizzled weight staging (global scratch) ----------------
__device__ __align__(16) float g_w0s[128 * 128];
__device__ __align__(16) float g_w1s[128 * 64];
__device__ __align__(16) float g_w2s[64 * 32];
__device__ __align__(16) float g_w3s[32 * 16];
__device__ __align__(16) float g_w4s[16 * 8];

// ---------------- packed f32x2 helpers ----------------
__device__ __forceinline__ ull pk2(float lo, float hi) {
    ull r; asm("mov.b64 %0, {%1, %2};" : "=l"(r) : "f"(lo), "f"(hi)); return r;
}
__device__ __forceinline__ void upk(ull v, float& lo, float& hi) {
    asm("mov.b64 {%0, %1}, %2;" : "=f"(lo), "=f"(hi) : "l"(v));
}
__device__ __forceinline__ void fma2(ull& d, ull a, ull b) {
    asm("fma.rn.f32x2 %0, %1, %2, %0;" : "+l"(d) : "l"(a), "l"(b));
}
__device__ __forceinline__ float lrelu(float x) { return fmaxf(x, 0.01f * x); }

// ---------------- prep: swizzle weights (quad-member interleave) ----------------
// layout per row k: ulonglong2 position (p*4 + m) holds lane-m's p-th ch quad
__global__ void cmfsm_prep(const float* __restrict__ w0, const float* __restrict__ w1,
                           const float* __restrict__ w2, const float* __restrict__ w3,
                           const float* __restrict__ w4) {
    int t = blockIdx.x * blockDim.x + threadIdx.x;
    int n = gridDim.x * blockDim.x;
    for (int i = t; i < 128 * 128; i += n) {
        int k = i >> 7, r = i & 127, pos = r >> 2, e = r & 3;
        int p = pos >> 2, m = pos & 3;
        int j = 32 * m + 4 * p + e;
        g_w0s[i] = w0[j * 128 + k];
    }
    for (int i = t; i < 128 * 64; i += n) {
        int k = i >> 6, r = i & 63, pos = r >> 2, e = r & 3;
        int p = pos >> 2, m = pos & 3;
        int j = 16 * m + 4 * p + e;
        g_w1s[i] = w1[j * 128 + k];
    }
    for (int i = t; i < 64 * 32; i += n) {
        int k = i >> 5, r = i & 31, pos = r >> 2, e = r & 3;
        int p = pos >> 2, m = pos & 3;
        int j = 8 * m + 4 * p + e;
        g_w2s[i] = w2[j * 64 + k];
    }
    for (int i = t; i < 32 * 16; i += n) {
        int k = i >> 4, r = i & 15, m = r >> 2, e = r & 3;
        int j = 4 * m + e;
        g_w3s[i] = w3[j * 32 + k];
    }
    for (int i = t; i < 16 * 8; i += n) {
        int k = i >> 3, r = i & 7, m = r >> 1, e = r & 1;
        int j = 2 * m + e;
        g_w4s[i] = w4[j * 16 + k];
    }
}

// ---------------- shared memory layout (floats) ----------------
#define SM_X   0
#define SM_W0  (64 * SX)               // 16640
#define SM_W1  (SM_W0 + 128 * 128)
#define SM_W2  (SM_W1 + 128 * 64)
#define SM_W3  (SM_W2 + 64 * 32)
#define SM_W4  (SM_W3 + 32 * 16)
#define SM_TOT (SM_W4 + 16 * 8)        // 43904 floats = 175616 B

__global__ void __launch_bounds__(256, 1)
cmfsm_main(const float* __restrict__ lr, const float* __restrict__ hr,
           const float* __restrict__ w5, const float* __restrict__ s2w0,
           const float* __restrict__ s2w1, const float* __restrict__ s2w2,
           const float* __restrict__ fw, float* __restrict__ out) {
    extern __shared__ __align__(16) float smem[];
    float* Xf  = smem + SM_X;
    float* sw0 = smem + SM_W0;
    float* sw1 = smem + SM_W1;
    float* sw2 = smem + SM_W2;
    float* sw3 = smem + SM_W3;
    float* sw4 = smem + SM_W4;

    const int tid = threadIdx.x;
    const int m = tid & 3;       // quad member: owns 1/4 of output channels
    const int u = tid >> 2;      // quad index: 0..63, pixels 4u..4u+3

    // weight copy gmem scratch -> smem (coalesced float4)
    {
        const float4* s0 = (const float4*)g_w0s; float4* d0 = (float4*)sw0;
        for (int i = tid; i < (128 * 128) / 4; i += 256) d0[i] = s0[i];
        const float4* s1 = (const float4*)g_w1s; float4* d1 = (float4*)sw1;
        for (int i = tid; i < (128 * 64) / 4; i += 256) d1[i] = s1[i];
        const float4* s2 = (const float4*)g_w2s; float4* d2 = (float4*)sw2;
        for (int i = tid; i < (64 * 32) / 4; i += 256) d2[i] = s2[i];
        const float4* s3 = (const float4*)g_w3s; float4* d3 = (float4*)sw3;
        for (int i = tid; i < (32 * 16) / 4; i += 256) d3[i] = s3[i];
        const float4* s4 = (const float4*)g_w4s; float4* d4 = (float4*)sw4;
        for (int i = tid; i < (16 * 8) / 4; i += 256) d4[i] = s4[i];
    }
    __syncthreads();

    const int px0 = blockIdx.x * 256 + 4 * u;   // quad's 4 adjacent pixels
    const int h   = px0 >> 10;
    const int w0c = px0 & 1023;
    const int lroff = ((h >> 1) << 9) + (w0c >> 1);

    const float* hrp = hr + px0;
    const float* lrp = lr + lroff;

    // ================= layer 1: 128 <- rep(128); lane owns ch [32m, 32m+32) =================
    ull A[64];   // [px][q]: A[px*16+q] = ch pair (32m+2q, 32m+2q+1)
#pragma unroll
    for (int i = 0; i < 64; i++) A[i] = 0ull;

#pragma unroll 1
    for (int k = 0; k < 32; k++) {
        float4 hv = *(const float4*)(hrp + k * NPX);
        float2 lv = *(const float2*)(lrp + k * LRN);
        float av[4] = { lv.x, lv.x, lv.y, lv.y };
        float bv[4] = { hv.x, hv.y, hv.z, hv.w };
        ull xa[4], xb[4], xp[4], xq[4];
#pragma unroll
        for (int px = 0; px < 4; px++) {
            float aa = av[px], bb = bv[px];
            float pp = aa * bb;
            float dd = aa - bb;
            float qq = dd * dd;
            xa[px] = pk2(aa, aa); xb[px] = pk2(bb, bb);
            xp[px] = pk2(pp, pp); xq[px] = pk2(qq, qq);
        }
        const ulonglong2* wA = (const ulonglong2*)(sw0 + k * 128) + m;
        const ulonglong2* wB = (const ulonglong2*)(sw0 + (32 + k) * 128) + m;
        const ulonglong2* wP = (const ulonglong2*)(sw0 + (64 + k) * 128) + m;
        const ulonglong2* wQ = (const ulonglong2*)(sw0 + (96 + k) * 128) + m;
#pragma unroll
        for (int p = 0; p < 8; p++) {
            ulonglong2 va = wA[4 * p], vb = wB[4 * p], vp = wP[4 * p], vq = wQ[4 * p];
#pragma unroll
            for (int px = 0; px < 4; px++) {
                fma2(A[px * 16 + 2 * p],     va.x, xa[px]);
                fma2(A[px * 16 + 2 * p + 1], va.y, xa[px]);
                fma2(A[px * 16 + 2 * p],     vb.x, xb[px]);
                fma2(A[px * 16 + 2 * p + 1], vb.y, xb[px]);
                fma2(A[px * 16 + 2 * p],     vp.x, xp[px]);
                fma2(A[px * 16 + 2 * p + 1], vp.y, xp[px]);
                fma2(A[px * 16 + 2 * p],     vq.x, xq[px]);
                fma2(A[px * 16 + 2 * p + 1], vq.y, xq[px]);
            }
        }
    }

    // ================= layer 2: 64 <- leaky(o1)(128), two 64-row halves =================
    ull B[32];   // B[px*8+q] = ch pair (16m+2q, 16m+2q+1)
#pragma unroll
    for (int i = 0; i < 32; i++) B[i] = 0ull;

#pragma unroll
    for (int half = 0; half < 2; half++) {
        if ((m >> 1) == half) {
            // write lrelu'd A slice: ch base 32m, rows (32m - 64*half) .. +31
            int rb = 32 * m - 64 * half;
#pragma unroll
            for (int q = 0; q < 16; q++) {
                float lo0, hi0, lo1, hi1, lo2, hi2, lo3, hi3;
                upk(A[0 * 16 + q], lo0, hi0); upk(A[1 * 16 + q], lo1, hi1);
                upk(A[2 * 16 + q], lo2, hi2); upk(A[3 * 16 + q], lo3, hi3);
                float4 vlo = { lrelu(lo0), lrelu(lo1), lrelu(lo2), lrelu(lo3) };
                float4 vhi = { lrelu(hi0), lrelu(hi1), lrelu(hi2), lrelu(hi3) };
                *(float4*)(Xf + (rb + 2 * q) * SX + 4 * u)     = vlo;
                *(float4*)(Xf + (rb + 2 * q + 1) * SX + 4 * u) = vhi;
            }
        }
        __syncwarp();
#pragma unroll 1
        for (int k2 = 0; k2 < 64; k2++) {
            int k = half * 64 + k2;
            float4 xv = *(const float4*)(Xf + k2 * SX + 4 * u);
            ull xd[4] = { pk2(xv.x, xv.x), pk2(xv.y, xv.y),
                          pk2(xv.z, xv.z), pk2(xv.w, xv.w) };
            const ulonglong2* wr = (const ulonglong2*)(sw1 + k * 64) + m;
#pragma unroll
            for (int p = 0; p < 4; p++) {
                ulonglong2 v = wr[4 * p];
#pragma unroll
                for (int px = 0; px < 4; px++) {
                    fma2(B[px * 8 + 2 * p],     v.x, xd[px]);
                    fma2(B[px * 8 + 2 * p + 1], v.y, xd[px]);
                }
            }
        }
        __syncwarp();
    }

    // ================= layer 3: 32 <- leaky(o2)(64) =================
    ull C[16];   // C[px*4+q] = ch pair (8m+2q, 8m+2q+1)
#pragma unroll
    for (int i = 0; i < 16; i++) C[i] = 0ull;
    {
        int rb = 16 * m;
#pragma unroll
        for (int q = 0; q < 8; q++) {
            float lo0, hi0, lo1, hi1, lo2, hi2, lo3, hi3;
            upk(B[0 * 8 + q], lo0, hi0); upk(B[1 * 8 + q], lo1, hi1);
            upk(B[2 * 8 + q], lo2, hi2); upk(B[3 * 8 + q], lo3, hi3);
            float4 vlo = { lrelu(lo0), lrelu(lo1), lrelu(lo2), lrelu(lo3) };
            float4 vhi = { lrelu(hi0), lrelu(hi1), lrelu(hi2), lrelu(hi3) };
            *(float4*)(Xf + (rb + 2 * q) * SX + 4 * u)     = vlo;
            *(float4*)(Xf + (rb + 2 * q + 1) * SX + 4 * u) = vhi;
        }
    }
    __syncwarp();
#pragma unroll 1
    for (int k = 0; k < 64; k++) {
        float4 xv = *(const float4*)(Xf + k * SX + 4 * u);
        ull xd[4] = { pk2(xv.x, xv.x), pk2(xv.y, xv.y),
                      pk2(xv.z, xv.z), pk2(xv.w, xv.w) };
        const ulonglong2* wr = (const ulonglong2*)(sw2 + k * 32) + m;
#pragma unroll
        for (int p = 0; p < 2; p++) {
            ulonglong2 v = wr[4 * p];
#pragma unroll
            for (int px = 0; px < 4; px++) {
                fma2(C[px * 4 + 2 * p],     v.x, xd[px]);
                fma2(C[px * 4 + 2 * p + 1], v.y, xd[px]);
            }
        }
    }
    __syncwarp();

    // ================= layer 4: 16 <- leaky(o3)(32) =================
    ull D[8];    // D[px*2+q] = ch pair (4m+2q, 4m+2q+1)
#pragma unroll
    for (int i = 0; i < 8; i++) D[i] = 0ull;
    {
        int rb = 8 * m;
#pragma unroll
        for (int q = 0; q < 4; q++) {
            float lo0, hi0, lo1, hi1, lo2, hi2, lo3, hi3;
            upk(C[0 * 4 + q], lo0, hi0); upk(C[1 * 4 + q], lo1, hi1);
            upk(C[2 * 4 + q], lo2, hi2); upk(C[3 * 4 + q], lo3, hi3);
            float4 vlo = { lrelu(lo0), lrelu(lo1), lrelu(lo2), lrelu(lo3) };
            float4 vhi = { lrelu(hi0), lrelu(hi1), lrelu(hi2), lrelu(hi3) };
            *(float4*)(Xf + (rb + 2 * q) * SX + 4 * u)     = vlo;
            *(float4*)(Xf + (rb + 2 * q + 1) * SX + 4 * u) = vhi;
        }
    }
    __syncwarp();
#pragma unroll 1
    for (int k = 0; k < 32; k++) {
        float4 xv = *(const float4*)(Xf + k * SX + 4 * u);
        ull xd[4] = { pk2(xv.x, xv.x), pk2(xv.y, xv.y),
                      pk2(xv.z, xv.z), pk2(xv.w, xv.w) };
        const ulonglong2* wr = (const ulonglong2*)(sw3 + k * 16) + m;
        ulonglong2 v = wr[0];
#pragma unroll
        for (int px = 0; px < 4; px++) {
            fma2(D[px * 2],     v.x, xd[px]);
            fma2(D[px * 2 + 1], v.y, xd[px]);
        }
    }
    __syncwarp();

    // ================= layer 5: 8 <- leaky(o4)(16), no output activation =================
    ull E[4];    // E[px] = ch pair (2m, 2m+1)
#pragma unroll
    for (int i = 0; i < 4; i++) E[i] = 0ull;
    {
        int rb = 4 * m;
#pragma unroll
        for (int q = 0; q < 2; q++) {
            float lo0, hi0, lo1, hi1, lo2, hi2, lo3, hi3;
            upk(D[0 * 2 + q], lo0, hi0); upk(D[1 * 2 + q], lo1, hi1);
            upk(D[2 * 2 + q], lo2, hi2); upk(D[3 * 2 + q], lo3, hi3);
            float4 vlo = { lrelu(lo0), lrelu(lo1), lrelu(lo2), lrelu(lo3) };
            float4 vhi = { lrelu(hi0), lrelu(hi1), lrelu(hi2), lrelu(hi3) };
            *(float4*)(Xf + (rb + 2 * q) * SX + 4 * u)     = vlo;
            *(float4*)(Xf + (rb + 2 * q + 1) * SX + 4 * u) = vhi;
        }
    }
    __syncwarp();
#pragma unroll 1
    for (int k = 0; k < 16; k++) {
        float4 xv = *(const float4*)(Xf + k * SX + 4 * u);
        ull xd[4] = { pk2(xv.x, xv.x), pk2(xv.y, xv.y),
                      pk2(xv.z, xv.z), pk2(xv.w, xv.w) };
        ull wv = *(const ull*)(sw4 + k * 8 + 2 * m);
#pragma unroll
        for (int px = 0; px < 4; px++) fma2(E[px], wv, xd[px]);
    }

    // ================= layer 6 + quad reduce: weights1 = w5 . o5 =================
    float w5a = w5[2 * m], w5b = w5[2 * m + 1];
    float part[4];
#pragma unroll
    for (int px = 0; px < 4; px++) {
        float lo, hi; upk(E[px], lo, hi);
        part[px] = w5a * lo + w5b * hi;
    }
#pragma unroll
    for (int px = 0; px < 4; px++) {
        part[px] += __shfl_xor_sync(0xffffffffu, part[px], 1);
        part[px] += __shfl_xor_sync(0xffffffffu, part[px], 2);
    }
    float w1v = (m == 0) ? part[0] : (m == 1) ? part[1] : (m == 2) ? part[2] : part[3];

    // ================= weights2: parity MLP =================
    float dx = ((w0c + m) & 1) ? 1.0f : -1.0f;
    float dy = (h & 1) ? 1.0f : -1.0f;
    const float nm = 1.41421356237309515f;
    float t0 = lrelu(s2w0[0] * dx + s2w0[1] * dy + s2w0[2] * nm);
    float t1 = lrelu(s2w0[3] * dx + s2w0[4] * dy + s2w0[5] * nm);
    float t2 = lrelu(s2w0[6] * dx + s2w0[7] * dy + s2w0[8] * nm);
    float u0 = lrelu(s2w1[0] * t0 + s2w1[1] * t1 + s2w1[2] * t2);
    float u1 = lrelu(s2w1[3] * t0 + s2w1[4] * t1 + s2w1[5] * t2);
    float w2v = s2w2[0] * u0 + s2w2[1] * u1;

    out[px0 + m] = fabsf(fw[0]) * w1v + fabsf(fw[1]) * w2v;
}

extern "C" void kernel_launch(void* const* d_in, const int* in_sizes, int n_in,
                              void* d_out, int out_size) {
    const float* lr   = (const float*)d_in[0];
    const float* hr   = (const float*)d_in[1];
    const float* w0   = (const float*)d_in[2];
    const float* w1   = (const float*)d_in[3];
    const float* w2   = (const float*)d_in[4];
    const float* w3   = (const float*)d_in[5];
    const float* w4   = (const float*)d_in[6];
    const float* w5   = (const float*)d_in[7];
    const float* s2w0 = (const float*)d_in[8];
    const float* s2w1 = (const float*)d_in[9];
    const float* s2w2 = (const float*)d_in[10];
    const float* fw   = (const float*)d_in[11];

    cmfsm_prep<<<64, 256>>>(w0, w1, w2, w3, w4);

    size_t smem_bytes = (size_t)SM_TOT * sizeof(float);
    cudaFuncSetAttribute(cmfsm_main, cudaFuncAttributeMaxDynamicSharedMemorySize,
                         (int)smem_bytes);
    cmfsm_main<<<NPX / 256, 256, smem_bytes>>>(lr, hr, w5, s2w0, s2w1, s2w2, fw,
                                               (float*)d_out);
}

// round 3
// speedup vs baseline: 1.3024x; 1.0661x over previous
#include <cuda_runtime.h>

typedef unsigned long long ull;

#define NPX (512 * 1024)
#define LRN (256 * 512)
#define SX  260               // X row stride in floats (1040B, 16B aligned)

// ---------------- swizzled weight staging (global scratch) ----------------
__device__ __align__(16) float g_w0s[128 * 128];
__device__ __align__(16) float g_w1s[128 * 64];
__device__ __align__(16) float g_w2s[64 * 32];
__device__ __align__(16) float g_w3s[32 * 16];
__device__ __align__(16) float g_w4s[16 * 8];

// ---------------- packed f32x2 helpers ----------------
__device__ __forceinline__ ull pk2(float lo, float hi) {
    ull r; asm("mov.b64 %0, {%1, %2};" : "=l"(r) : "f"(lo), "f"(hi)); return r;
}
__device__ __forceinline__ void upk(ull v, float& lo, float& hi) {
    asm("mov.b64 {%0, %1}, %2;" : "=f"(lo), "=f"(hi) : "l"(v));
}
__device__ __forceinline__ void fma2(ull& d, ull a, ull b) {
    asm("fma.rn.f32x2 %0, %1, %2, %0;" : "+l"(d) : "l"(a), "l"(b));
}
__device__ __forceinline__ float lrelu(float x) { return fmaxf(x, 0.01f * x); }

// ---------------- prep: swizzle weights (quad-member interleave) ----------------
__global__ void cmfsm_prep(const float* __restrict__ w0, const float* __restrict__ w1,
                           const float* __restrict__ w2, const float* __restrict__ w3,
                           const float* __restrict__ w4) {
    int t = blockIdx.x * blockDim.x + threadIdx.x;
    int n = gridDim.x * blockDim.x;
    for (int i = t; i < 128 * 128; i += n) {
        int k = i >> 7, r = i & 127, pos = r >> 2, e = r & 3;
        int p = pos >> 2, m = pos & 3;
        int j = 32 * m + 4 * p + e;
        g_w0s[i] = w0[j * 128 + k];
    }
    for (int i = t; i < 128 * 64; i += n) {
        int k = i >> 6, r = i & 63, pos = r >> 2, e = r & 3;
        int p = pos >> 2, m = pos & 3;
        int j = 16 * m + 4 * p + e;
        g_w1s[i] = w1[j * 128 + k];
    }
    for (int i = t; i < 64 * 32; i += n) {
        int k = i >> 5, r = i & 31, pos = r >> 2, e = r & 3;
        int p = pos >> 2, m = pos & 3;
        int j = 8 * m + 4 * p + e;
        g_w2s[i] = w2[j * 64 + k];
    }
    for (int i = t; i < 32 * 16; i += n) {
        int k = i >> 4, r = i & 15, m = r >> 2, e = r & 3;
        int j = 4 * m + e;
        g_w3s[i] = w3[j * 32 + k];
    }
    for (int i = t; i < 16 * 8; i += n) {
        int k = i >> 3, r = i & 7, m = r >> 1, e = r & 1;
        int j = 2 * m + e;
        g_w4s[i] = w4[j * 16 + k];
    }
}

// ---------------- shared memory layout (floats) ----------------
#define SM_X   0
#define SM_W0  (64 * SX)               // 16640
#define SM_W1  (SM_W0 + 128 * 128)
#define SM_W2  (SM_W1 + 128 * 64)
#define SM_W3  (SM_W2 + 64 * 32)
#define SM_W4  (SM_W3 + 32 * 16)
#define SM_LR  (SM_W4 + 16 * 8)        // lr staging: 32 ch x 128 px
#define SM_TOT (SM_LR + 32 * 128)      // 48000 floats = 192000 B

__global__ void __launch_bounds__(256, 1)
cmfsm_main(const float* __restrict__ lr, const float* __restrict__ hr,
           const float* __restrict__ w5, const float* __restrict__ s2w0,
           const float* __restrict__ s2w1, const float* __restrict__ s2w2,
           const float* __restrict__ fw, float* __restrict__ out) {
    extern __shared__ __align__(16) float smem[];
    float* Xf  = smem + SM_X;
    float* sw0 = smem + SM_W0;
    float* sw1 = smem + SM_W1;
    float* sw2 = smem + SM_W2;
    float* sw3 = smem + SM_W3;
    float* sw4 = smem + SM_W4;
    float* sLR = smem + SM_LR;

    const int tid = threadIdx.x;
    const int m = tid & 3;       // quad member: owns 1/4 of output channels
    const int u = tid >> 2;      // quad index: 0..63, pixels 4u..4u+3

    const int pxb = blockIdx.x * 256;    // block pixel base (one hr row: 4 blocks/row)
    const int hb  = pxb >> 10;
    const int wb  = pxb & 1023;
    const int lrbase = ((hb >> 1) << 9) + (wb >> 1);   // 128 consecutive lr floats

    // -------- stage activations (hr -> X rows 0..31, lr -> sLR) + weight copy --------
    // All LDGs batched before the single __syncthreads: DRAM latency paid once/block.
    {
        // hr: 32 ch x 256 px
        for (int i = tid; i < 32 * 64; i += 256) {
            int c = i >> 6, g = i & 63;
            float4 v = *(const float4*)(hr + c * NPX + pxb + 4 * g);
            *(float4*)(Xf + c * SX + 4 * g) = v;
        }
        // lr: 32 ch x 128 px
        for (int i = tid; i < 32 * 32; i += 256) {
            int c = i >> 5, g = i & 31;
            float4 v = *(const float4*)(lr + c * LRN + lrbase + 4 * g);
            *(float4*)(sLR + c * 128 + 4 * g) = v;
        }
        // weights (L2-resident scratch) -> smem
        const float4* s0 = (const float4*)g_w0s; float4* d0 = (float4*)sw0;
        for (int i = tid; i < (128 * 128) / 4; i += 256) d0[i] = s0[i];
        const float4* s1 = (const float4*)g_w1s; float4* d1 = (float4*)sw1;
        for (int i = tid; i < (128 * 64) / 4; i += 256) d1[i] = s1[i];
        const float4* s2 = (const float4*)g_w2s; float4* d2 = (float4*)sw2;
        for (int i = tid; i < (64 * 32) / 4; i += 256) d2[i] = s2[i];
        const float4* s3 = (const float4*)g_w3s; float4* d3 = (float4*)sw3;
        for (int i = tid; i < (32 * 16) / 4; i += 256) d3[i] = s3[i];
        const float4* s4 = (const float4*)g_w4s; float4* d4 = (float4*)sw4;
        for (int i = tid; i < (16 * 8) / 4; i += 256) d4[i] = s4[i];
    }
    __syncthreads();

    const int px0 = pxb + 4 * u;   // quad's 4 adjacent pixels

    // ================= layer 1: 128 <- rep(128); lane owns ch [32m, 32m+32) =================
    ull A[64];   // A[px*16+q] = ch pair (32m+2q, 32m+2q+1)
#pragma unroll
    for (int i = 0; i < 64; i++) A[i] = 0ull;

#pragma unroll 1
    for (int k = 0; k < 32; k++) {
        float4 hv = *(const float4*)(Xf + k * SX + 4 * u);       // quad-broadcast LDS.128
        float2 lv = *(const float2*)(sLR + k * 128 + 2 * u);     // quad-broadcast LDS.64
        float av[4] = { lv.x, lv.x, lv.y, lv.y };
        float bv[4] = { hv.x, hv.y, hv.z, hv.w };
        ull xa[4], xb[4], xp[4], xq[4];
#pragma unroll
        for (int px = 0; px < 4; px++) {
            float aa = av[px], bb = bv[px];
            float pp = aa * bb;
            float dd = aa - bb;
            float qq = dd * dd;
            xa[px] = pk2(aa, aa); xb[px] = pk2(bb, bb);
            xp[px] = pk2(pp, pp); xq[px] = pk2(qq, qq);
        }
        const ulonglong2* wA = (const ulonglong2*)(sw0 + k * 128) + m;
        const ulonglong2* wB = (const ulonglong2*)(sw0 + (32 + k) * 128) + m;
        const ulonglong2* wP = (const ulonglong2*)(sw0 + (64 + k) * 128) + m;
        const ulonglong2* wQ = (const ulonglong2*)(sw0 + (96 + k) * 128) + m;
#pragma unroll
        for (int p = 0; p < 8; p++) {
            ulonglong2 va = wA[4 * p], vb = wB[4 * p], vp = wP[4 * p], vq = wQ[4 * p];
#pragma unroll
            for (int px = 0; px < 4; px++) {
                fma2(A[px * 16 + 2 * p],     va.x, xa[px]);
                fma2(A[px * 16 + 2 * p + 1], va.y, xa[px]);
                fma2(A[px * 16 + 2 * p],     vb.x, xb[px]);
                fma2(A[px * 16 + 2 * p + 1], vb.y, xb[px]);
                fma2(A[px * 16 + 2 * p],     vp.x, xp[px]);
                fma2(A[px * 16 + 2 * p + 1], vp.y, xp[px]);
                fma2(A[px * 16 + 2 * p],     vq.x, xq[px]);
                fma2(A[px * 16 + 2 * p + 1], vq.y, xq[px]);
            }
        }
    }

    // ================= layer 2: 64 <- leaky(o1)(128), two 64-row halves =================
    ull B[32];   // B[px*8+q] = ch pair (16m+2q, 16m+2q+1)
#pragma unroll
    for (int i = 0; i < 32; i++) B[i] = 0ull;

#pragma unroll
    for (int half = 0; half < 2; half++) {
        if ((m >> 1) == half) {
            int rb = 32 * m - 64 * half;
#pragma unroll
            for (int q = 0; q < 16; q++) {
                float lo0, hi0, lo1, hi1, lo2, hi2, lo3, hi3;
                upk(A[0 * 16 + q], lo0, hi0); upk(A[1 * 16 + q], lo1, hi1);
                upk(A[2 * 16 + q], lo2, hi2); upk(A[3 * 16 + q], lo3, hi3);
                float4 vlo = { lrelu(lo0), lrelu(lo1), lrelu(lo2), lrelu(lo3) };
                float4 vhi = { lrelu(hi0), lrelu(hi1), lrelu(hi2), lrelu(hi3) };
                *(float4*)(Xf + (rb + 2 * q) * SX + 4 * u)     = vlo;
                *(float4*)(Xf + (rb + 2 * q + 1) * SX + 4 * u) = vhi;
            }
        }
        __syncwarp();
#pragma unroll 1
        for (int k2 = 0; k2 < 64; k2++) {
            int k = half * 64 + k2;
            float4 xv = *(const float4*)(Xf + k2 * SX + 4 * u);
            ull xd[4] = { pk2(xv.x, xv.x), pk2(xv.y, xv.y),
                          pk2(xv.z, xv.z), pk2(xv.w, xv.w) };
            const ulonglong2* wr = (const ulonglong2*)(sw1 + k * 64) + m;
#pragma unroll
            for (int p = 0; p < 4; p++) {
                ulonglong2 v = wr[4 * p];
#pragma unroll
                for (int px = 0; px < 4; px++) {
                    fma2(B[px * 8 + 2 * p],     v.x, xd[px]);
                    fma2(B[px * 8 + 2 * p + 1], v.y, xd[px]);
                }
            }
        }
        __syncwarp();
    }

    // ================= layer 3: 32 <- leaky(o2)(64) =================
    ull C[16];
#pragma unroll
    for (int i = 0; i < 16; i++) C[i] = 0ull;
    {
        int rb = 16 * m;
#pragma unroll
        for (int q = 0; q < 8; q++) {
            float lo0, hi0, lo1, hi1, lo2, hi2, lo3, hi3;
            upk(B[0 * 8 + q], lo0, hi0); upk(B[1 * 8 + q], lo1, hi1);
            upk(B[2 * 8 + q], lo2, hi2); upk(B[3 * 8 + q], lo3, hi3);
            float4 vlo = { lrelu(lo0), lrelu(lo1), lrelu(lo2), lrelu(lo3) };
            float4 vhi = { lrelu(hi0), lrelu(hi1), lrelu(hi2), lrelu(hi3) };
            *(float4*)(Xf + (rb + 2 * q) * SX + 4 * u)     = vlo;
            *(float4*)(Xf + (rb + 2 * q + 1) * SX + 4 * u) = vhi;
        }
    }
    __syncwarp();
#pragma unroll 1
    for (int k = 0; k < 64; k++) {
        float4 xv = *(const float4*)(Xf + k * SX + 4 * u);
        ull xd[4] = { pk2(xv.x, xv.x), pk2(xv.y, xv.y),
                      pk2(xv.z, xv.z), pk2(xv.w, xv.w) };
        const ulonglong2* wr = (const ulonglong2*)(sw2 + k * 32) + m;
#pragma unroll
        for (int p = 0; p < 2; p++) {
            ulonglong2 v = wr[4 * p];
#pragma unroll
            for (int px = 0; px < 4; px++) {
                fma2(C[px * 4 + 2 * p],     v.x, xd[px]);
                fma2(C[px * 4 + 2 * p + 1], v.y, xd[px]);
            }
        }
    }
    __syncwarp();

    // ================= layer 4: 16 <- leaky(o3)(32) =================
    ull D[8];
#pragma unroll
    for (int i = 0; i < 8; i++) D[i] = 0ull;
    {
        int rb = 8 * m;
#pragma unroll
        for (int q = 0; q < 4; q++) {
            float lo0, hi0, lo1, hi1, lo2, hi2, lo3, hi3;
            upk(C[0 * 4 + q], lo0, hi0); upk(C[1 * 4 + q], lo1, hi1);
            upk(C[2 * 4 + q], lo2, hi2); upk(C[3 * 4 + q], lo3, hi3);
            float4 vlo = { lrelu(lo0), lrelu(lo1), lrelu(lo2), lrelu(lo3) };
            float4 vhi = { lrelu(hi0), lrelu(hi1), lrelu(hi2), lrelu(hi3) };
            *(float4*)(Xf + (rb + 2 * q) * SX + 4 * u)     = vlo;
            *(float4*)(Xf + (rb + 2 * q + 1) * SX + 4 * u) = vhi;
        }
    }
    __syncwarp();
#pragma unroll 1
    for (int k = 0; k < 32; k++) {
        float4 xv = *(const float4*)(Xf + k * SX + 4 * u);
        ull xd[4] = { pk2(xv.x, xv.x), pk2(xv.y, xv.y),
                      pk2(xv.z, xv.z), pk2(xv.w, xv.w) };
        const ulonglong2* wr = (const ulonglong2*)(sw3 + k * 16) + m;
        ulonglong2 v = wr[0];
#pragma unroll
        for (int px = 0; px < 4; px++) {
            fma2(D[px * 2],     v.x, xd[px]);
            fma2(D[px * 2 + 1], v.y, xd[px]);
        }
    }
    __syncwarp();

    // ================= layer 5: 8 <- leaky(o4)(16) =================
    ull E[4];
#pragma unroll
    for (int i = 0; i < 4; i++) E[i] = 0ull;
    {
        int rb = 4 * m;
#pragma unroll
        for (int q = 0; q < 2; q++) {
            float lo0, hi0, lo1, hi1, lo2, hi2, lo3, hi3;
            upk(D[0 * 2 + q], lo0, hi0); upk(D[1 * 2 + q], lo1, hi1);
            upk(D[2 * 2 + q], lo2, hi2); upk(D[3 * 2 + q], lo3, hi3);
            float4 vlo = { lrelu(lo0), lrelu(lo1), lrelu(lo2), lrelu(lo3) };
            float4 vhi = { lrelu(hi0), lrelu(hi1), lrelu(hi2), lrelu(hi3) };
            *(float4*)(Xf + (rb + 2 * q) * SX + 4 * u)     = vlo;
            *(float4*)(Xf + (rb + 2 * q + 1) * SX + 4 * u) = vhi;
        }
    }
    __syncwarp();
#pragma unroll 1
    for (int k = 0; k < 16; k++) {
        float4 xv = *(const float4*)(Xf + k * SX + 4 * u);
        ull xd[4] = { pk2(xv.x, xv.x), pk2(xv.y, xv.y),
                      pk2(xv.z, xv.z), pk2(xv.w, xv.w) };
        ull wv = *(const ull*)(sw4 + k * 8 + 2 * m);
#pragma unroll
        for (int px = 0; px < 4; px++) fma2(E[px], wv, xd[px]);
    }

    // ================= layer 6 + quad reduce =================
    float w5a = w5[2 * m], w5b = w5[2 * m + 1];
    float part[4];
#pragma unroll
    for (int px = 0; px < 4; px++) {
        float lo, hi; upk(E[px], lo, hi);
        part[px] = w5a * lo + w5b * hi;
    }
#pragma unroll
    for (int px = 0; px < 4; px++) {
        part[px] += __shfl_xor_sync(0xffffffffu, part[px], 1);
        part[px] += __shfl_xor_sync(0xffffffffu, part[px], 2);
    }
    float w1v = (m == 0) ? part[0] : (m == 1) ? part[1] : (m == 2) ? part[2] : part[3];

    // ================= weights2: parity MLP =================
    float dx = ((wb + 4 * u + m) & 1) ? 1.0f : -1.0f;
    float dy = (hb & 1) ? 1.0f : -1.0f;
    const float nm = 1.41421356237309515f;
    float t0 = lrelu(s2w0[0] * dx + s2w0[1] * dy + s2w0[2] * nm);
    float t1 = lrelu(s2w0[3] * dx + s2w0[4] * dy + s2w0[5] * nm);
    float t2 = lrelu(s2w0[6] * dx + s2w0[7] * dy + s2w0[8] * nm);
    float u0 = lrelu(s2w1[0] * t0 + s2w1[1] * t1 + s2w1[2] * t2);
    float u1 = lrelu(s2w1[3] * t0 + s2w1[4] * t1 + s2w1[5] * t2);
    float w2v = s2w2[0] * u0 + s2w2[1] * u1;

    out[px0 + m] = fabsf(fw[0]) * w1v + fabsf(fw[1]) * w2v;
}

extern "C" void kernel_launch(void* const* d_in, const int* in_sizes, int n_in,
                              void* d_out, int out_size) {
    const float* lr   = (const float*)d_in[0];
    const float* hr   = (const float*)d_in[1];
    const float* w0   = (const float*)d_in[2];
    const float* w1   = (const float*)d_in[3];
    const float* w2   = (const float*)d_in[4];
    const float* w3   = (const float*)d_in[5];
    const float* w4   = (const float*)d_in[6];
    const float* w5   = (const float*)d_in[7];
    const float* s2w0 = (const float*)d_in[8];
    const float* s2w1 = (const float*)d_in[9];
    const float* s2w2 = (const float*)d_in[10];
    const float* fw   = (const float*)d_in[11];

    cmfsm_prep<<<64, 256>>>(w0, w1, w2, w3, w4);

    size_t smem_bytes = (size_t)SM_TOT * sizeof(float);
    cudaFuncSetAttribute(cmfsm_main, cudaFuncAttributeMaxDynamicSharedMemorySize,
                         (int)smem_bytes);
    cmfsm_main<<<NPX / 256, 256, smem_bytes>>>(lr, hr, w5, s2w0, s2w1, s2w2, fw,
                                               (float*)d_out);
}

// round 6
// speedup vs baseline: 2.4004x; 1.8431x over previous
#include <cuda_runtime.h>
#include <cstdint>

typedef unsigned u32;

#define NPX (512 * 1024)
#define LRN (256 * 512)
#define NTILES 4096            // 4096 tiles x 128 px
#define BSTR 136               // act buffer row stride (floats)

// ---------------- tf32 weights (padded layouts) in global scratch ----------------
__device__ __align__(16) u32 g_wt0[128 * 132];
__device__ __align__(16) u32 g_wt1[64 * 132];
__device__ __align__(16) u32 g_wt2[32 * 68];
__device__ __align__(16) u32 g_wt3[16 * 36];

__device__ __forceinline__ u32 f2tf(float f) {
    u32 r; asm("cvt.rna.tf32.f32 %0, %1;" : "=r"(r) : "f"(f)); return r;
}
__device__ __forceinline__ float lrelu(float x) { return fmaxf(x, 0.01f * x); }

// ---------------- prep: fp32 -> tf32 padded weight layouts ----------------
__global__ void cmfsm_prep(const float* __restrict__ w0, const float* __restrict__ w1,
                           const float* __restrict__ w2, const float* __restrict__ w3) {
    int t = blockIdx.x * blockDim.x + threadIdx.x;
    int n = gridDim.x * blockDim.x;
    for (int i = t; i < 128 * 128; i += n) { int j = i >> 7, k = i & 127; g_wt0[j * 132 + k] = f2tf(w0[i]); }
    for (int i = t; i < 64 * 128;  i += n) { int j = i >> 7, k = i & 127; g_wt1[j * 132 + k] = f2tf(w1[i]); }
    for (int i = t; i < 32 * 64;   i += n) { int j = i >> 6, k = i & 63;  g_wt2[j * 68  + k] = f2tf(w2[i]); }
    for (int i = t; i < 16 * 32;   i += n) { int j = i >> 5, k = i & 31;  g_wt3[j * 36  + k] = f2tf(w3[i]); }
}

// ---------------- smem layout (bytes) ----------------
#define OBUF  0                         // act buffer: 128 rows x 136 f32 = 69632
#define OSW0  69632                     // 128x132 u32 = 67584
#define OSW1  137216                    // 64x132 = 33792
#define OSW2  171008                    // 32x68  = 8704
#define OSW3  179712                    // 16x36  = 2304
#define OSACT 182016                    // 128 px x 17 f32 = 8704
#define SMEMSZ 190720

// ---------------- mma.m16n8k8 tf32 ----------------
__device__ __forceinline__ void mma8(float* c, const u32* a, u32 b0, u32 b1) {
    asm volatile(
        "mma.sync.aligned.m16n8k8.row.col.f32.tf32.tf32.f32 "
        "{%0,%1,%2,%3}, {%4,%5,%6,%7}, {%8,%9}, {%0,%1,%2,%3};"
        : "+f"(c[0]), "+f"(c[1]), "+f"(c[2]), "+f"(c[3])
        : "r"(a[0]), "r"(a[1]), "r"(a[2]), "r"(a[3]), "r"(b0), "r"(b1));
}

// A-fragment: W[m0+r][k0+c], +8 rows, +4 cols  (r=lane>>2, c=lane&3)
__device__ __forceinline__ void lda(const u32* W, int S, int m0, int k0, int lane, u32* a) {
    int r = lane >> 2, c = lane & 3;
    const u32* p = W + (m0 + r) * S + k0 + c;
    a[0] = p[0];
    a[2] = p[4];
    a[1] = p[8 * S];
    a[3] = p[8 * S + 4];
}

// GEMM: C[MT][NT][4] += Wtf32 @ split(act).  K = 8*KT.
template <int MT, int NT, int KT, int WS>
__device__ __forceinline__ void gemm(const u32* W, const float* buf, float* C,
                                     int m0, int px0, int lane) {
    const int r = lane >> 2, c = lane & 3;
#pragma unroll 1
    for (int kt = 0; kt < KT; kt++) {
        const int k0 = kt * 8;
        u32 a[MT][4];
#pragma unroll
        for (int mt = 0; mt < MT; mt++) lda(W, WS, m0 + 16 * mt, k0, lane, a[mt]);
#pragma unroll
        for (int nt = 0; nt < NT; nt++) {
            float y0 = buf[(k0 + c) * BSTR + px0 + 8 * nt + r];
            float y1 = buf[(k0 + 4 + c) * BSTR + px0 + 8 * nt + r];
            u32 h0 = f2tf(y0), h1 = f2tf(y1);
            u32 l0 = f2tf(y0 - __uint_as_float(h0));
            u32 l1 = f2tf(y1 - __uint_as_float(h1));
#pragma unroll
            for (int mt = 0; mt < MT; mt++) {
                mma8(C + (mt * NT + nt) * 4, a[mt], h0, h1);
                mma8(C + (mt * NT + nt) * 4, a[mt], l0, l1);
            }
        }
    }
}

// epilogue: lrelu(C) -> buf (fp32), in place over inputs (caller syncs first)
template <int MT, int NT>
__device__ __forceinline__ void epi(float* buf, const float* C, int m0, int px0, int lane) {
    const int r = lane >> 2, c = lane & 3;
#pragma unroll
    for (int mt = 0; mt < MT; mt++)
#pragma unroll
        for (int nt = 0; nt < NT; nt++) {
            const float* cc = C + (mt * NT + nt) * 4;
            int ch = m0 + 16 * mt + r;
            int px = px0 + 8 * nt + 2 * c;
            float2 v0 = { lrelu(cc[0]), lrelu(cc[1]) };
            float2 v1 = { lrelu(cc[2]), lrelu(cc[3]) };
            *(float2*)(buf + ch * BSTR + px)       = v0;
            *(float2*)(buf + (ch + 8) * BSTR + px) = v1;
        }
}

__global__ void __launch_bounds__(256, 1)
cmfsm_main(const float* __restrict__ lr, const float* __restrict__ hr,
           const float* __restrict__ w4, const float* __restrict__ w5,
           const float* __restrict__ s2w0, const float* __restrict__ s2w1,
           const float* __restrict__ s2w2, const float* __restrict__ fw,
           float* __restrict__ out) {
    extern __shared__ __align__(16) char sm8[];
    float* buf  = (float*)(sm8 + OBUF);
    u32*  sw0   = (u32*)(sm8 + OSW0);
    u32*  sw1   = (u32*)(sm8 + OSW1);
    u32*  sw2   = (u32*)(sm8 + OSW2);
    u32*  sw3   = (u32*)(sm8 + OSW3);
    float* sact = (float*)(sm8 + OSACT);

    const int tid  = threadIdx.x;
    const int wid  = tid >> 5;
    const int lane = tid & 31;

    // weights: L2 scratch -> smem, once per (persistent) block
    {
        const uint4* s0 = (const uint4*)g_wt0; uint4* d0 = (uint4*)sw0;
        for (int i = tid; i < 4224; i += 256) d0[i] = s0[i];
        const uint4* s1 = (const uint4*)g_wt1; uint4* d1 = (uint4*)sw1;
        for (int i = tid; i < 2112; i += 256) d1[i] = s1[i];
        const uint4* s2 = (const uint4*)g_wt2; uint4* d2 = (uint4*)sw2;
        for (int i = tid; i < 544; i += 256) d2[i] = s2[i];
        const uint4* s3 = (const uint4*)g_wt3; uint4* d3 = (uint4*)sw3;
        for (int i = tid; i < 144; i += 256) d3[i] = s3[i];
    }
    __syncthreads();

    for (int tile = blockIdx.x; tile < NTILES; tile += gridDim.x) {
        const int pxb = tile << 7;
        const int hb  = pxb >> 10;
        const int wbp = pxb & 1023;

        // ---- rep build: rows 0-31 a, 32-63 b, 64-95 a*b, 96-127 (a-b)^2 ----
        {
            const int g  = tid >> 7;          // 0..1 -> 16 channels each
            const int px = tid & 127;
            const int li = ((hb >> 1) << 9) + ((wbp + px) >> 1);
            const float* hp = hr + (size_t)(16 * g) * NPX + (pxb + px);
            const float* lp = lr + (size_t)(16 * g) * LRN + li;
#pragma unroll
            for (int i = 0; i < 16; i++) {
                float a = lp[(size_t)i * LRN];
                float b = hp[(size_t)i * NPX];
                int cch = 16 * g + i;
                buf[cch * BSTR + px]        = a;
                buf[(32 + cch) * BSTR + px] = b;
                buf[(64 + cch) * BSTR + px] = a * b;
                float d = a - b;
                buf[(96 + cch) * BSTR + px] = d * d;
            }
        }
        __syncthreads();

        // ---- GEMM1: 128 <- rep(128) ----
        {
            float C1[2 * 8 * 4];
#pragma unroll
            for (int i = 0; i < 64; i++) C1[i] = 0.f;
            int m0 = 32 * (wid & 3), px0 = 64 * (wid >> 2);
            gemm<2, 8, 16, 132>(sw0, buf, C1, m0, px0, lane);
            __syncthreads();
            epi<2, 8>(buf, C1, m0, px0, lane);
        }
        __syncthreads();

        // ---- GEMM2: 64 <- act1(128) ----
        {
            float C2[2 * 4 * 4];
#pragma unroll
            for (int i = 0; i < 32; i++) C2[i] = 0.f;
            int m0 = 32 * (wid & 1), px0 = 32 * (wid >> 1);
            gemm<2, 4, 16, 132>(sw1, buf, C2, m0, px0, lane);
            __syncthreads();
            epi<2, 4>(buf, C2, m0, px0, lane);
        }
        __syncthreads();

        // ---- GEMM3: 32 <- act2(64) ----
        {
            float C3[1 * 4 * 4];
#pragma unroll
            for (int i = 0; i < 16; i++) C3[i] = 0.f;
            int m0 = 16 * (wid & 1), px0 = 32 * (wid >> 1);
            gemm<1, 4, 8, 68>(sw2, buf, C3, m0, px0, lane);
            __syncthreads();
            epi<1, 4>(buf, C3, m0, px0, lane);
        }
        __syncthreads();

        // ---- GEMM4: 16 <- act3(32); each warp does 16 px (NT=2) -> SACT [px][16] ----
        {
            float C4[2 * 4];
#pragma unroll
            for (int i = 0; i < 8; i++) C4[i] = 0.f;
            int px0 = 16 * wid;
            gemm<1, 2, 4, 36>(sw3, buf, C4, 0, px0, lane);
            const int r = lane >> 2, c = lane & 3;
#pragma unroll
            for (int nt = 0; nt < 2; nt++) {
                const float* cc = C4 + nt * 4;
                int px = px0 + 8 * nt + 2 * c;
                sact[px * 17 + r]           = lrelu(cc[0]);
                sact[(px + 1) * 17 + r]     = lrelu(cc[1]);
                sact[px * 17 + r + 8]       = lrelu(cc[2]);
                sact[(px + 1) * 17 + r + 8] = lrelu(cc[3]);
            }
        }
        __syncthreads();

        // ---- scalar finish: layers 5,6 + weights2 + fuse ----
        if (tid < 128) {
            const float* o4 = sact + tid * 17;
            float w1v = 0.f;
#pragma unroll
            for (int cc = 0; cc < 8; cc++) {
                float n5 = 0.f;
#pragma unroll
                for (int k = 0; k < 16; k++) n5 = fmaf(w4[cc * 16 + k], o4[k], n5);
                w1v = fmaf(w5[cc], n5, w1v);
            }
            float dx = ((wbp + tid) & 1) ? 1.0f : -1.0f;
            float dy = (hb & 1) ? 1.0f : -1.0f;
            const float nm = 1.41421356237309515f;
            float t0 = lrelu(s2w0[0] * dx + s2w0[1] * dy + s2w0[2] * nm);
            float t1 = lrelu(s2w0[3] * dx + s2w0[4] * dy + s2w0[5] * nm);
            float t2 = lrelu(s2w0[6] * dx + s2w0[7] * dy + s2w0[8] * nm);
            float u0 = lrelu(s2w1[0] * t0 + s2w1[1] * t1 + s2w1[2] * t2);
            float u1 = lrelu(s2w1[3] * t0 + s2w1[4] * t1 + s2w1[5] * t2);
            float w2v = s2w2[0] * u0 + s2w2[1] * u1;
            out[pxb + tid] = fabsf(fw[0]) * w1v + fabsf(fw[1]) * w2v;
        }
        __syncthreads();
    }
}

extern "C" void kernel_launch(void* const* d_in, const int* in_sizes, int n_in,
                              void* d_out, int out_size) {
    const float* lr   = (const float*)d_in[0];
    const float* hr   = (const float*)d_in[1];
    const float* w0   = (const float*)d_in[2];
    const float* w1   = (const float*)d_in[3];
    const float* w2   = (const float*)d_in[4];
    const float* w3   = (const float*)d_in[5];
    const float* w4   = (const float*)d_in[6];
    const float* w5   = (const float*)d_in[7];
    const float* s2w0 = (const float*)d_in[8];
    const float* s2w1 = (const float*)d_in[9];
    const float* s2w2 = (const float*)d_in[10];
    const float* fw   = (const float*)d_in[11];

    cmfsm_prep<<<64, 256>>>(w0, w1, w2, w3);

    int sms = 148;
    cudaDeviceGetAttribute(&sms, cudaDevAttrMultiProcessorCount, 0);
    if (sms > NTILES) sms = NTILES;

    cudaFuncSetAttribute(cmfsm_main, cudaFuncAttributeMaxDynamicSharedMemorySize, SMEMSZ);
    cmfsm_main<<<sms, 256, SMEMSZ>>>(lr, hr, w4, w5, s2w0, s2w1, s2w2, fw, (float*)d_out);
}